// round 2
// baseline (speedup 1.0000x reference)
#include <cuda_runtime.h>

#define QN   2048
#define EN   256
#define TOTC 40
#define NB   8
#define LMAXC 5
#define NH   8

// ---------------- scratch (static device globals; no allocation) ----------------
__device__ float g_trans [TOTC*QN*3];
__device__ float g_hidden[TOTC*QN*EN];
__device__ float g_kk    [TOTC*QN*EN];
__device__ float g_kp    [TOTC*QN*EN];
__device__ float g_vp    [TOTC*QN*EN];
__device__ float g_ego   [2][NB*QN*EN];
__device__ float g_qp    [NB*QN*EN];
__device__ float g_ctx   [NB*QN*EN];
__device__ float g_freq  [EN];
__device__ int   g_cav_batch[TOTC];
__device__ int   g_cav_local[TOTC];
__device__ int   g_batch_n  [NB];
__device__ int   g_batch_off[NB];

// ---------------- setup: offsets, per-cav maps, sine frequencies ----------------
__global__ void setup_kernel(const long long* __restrict__ rl64) {
    int t = threadIdx.x;
    if (t == 0) {
        // defensive dtype check: record_len may arrive as int64 or int32
        bool ok64 = true;
        for (int b = 0; b < NB; b++) {
            long long v = rl64[b];
            if (v < 1 || v > LMAXC) ok64 = false;
        }
        const int* rl32 = (const int*)rl64;
        int acc = 0;
        for (int c = 0; c < TOTC; c++) { g_cav_batch[c] = 0; g_cav_local[c] = 0; }
        for (int b = 0; b < NB; b++) {
            int n = ok64 ? (int)rl64[b] : rl32[b];
            if (n < 1) n = 1;
            if (n > LMAXC) n = LMAXC;
            g_batch_n[b] = n; g_batch_off[b] = acc;
            for (int l = 0; l < n; l++) {
                int c = acc + l;
                if (c < TOTC) { g_cav_batch[c] = b; g_cav_local[c] = l; }
            }
            acc += n;
        }
    }
    for (int j = t; j < EN; j += blockDim.x) {
        float ex = (2.0f * (float)(j >> 1)) / (float)EN;   // 2*floor(j/2)/E
        g_freq[j] = 6.283185307179586f * expf(-ex * 9.210340371976184f); // 2pi / 10000^ex
    }
}

// ---------------- trans = sigmoid(T @ homo)[:3] ----------------
__global__ void trans_kernel(const float* __restrict__ rp, const float* __restrict__ ptm) {
    int idx = blockIdx.x * blockDim.x + threadIdx.x;   // (c,q) flattened
    if (idx >= TOTC * QN) return;
    int c = idx / QN;
    int b = g_cav_batch[c], l = g_cav_local[c];
    float r0 = rp[idx*3+0] * 281.6f - 140.8f;
    float r1 = rp[idx*3+1] *  80.0f -  40.0f;
    float r2 = rp[idx*3+2] *   4.0f -   3.0f;
    const float* T = ptm + (size_t)((b * LMAXC + l) * LMAXC) * 16;  // [b][l][0][:][:]
    #pragma unroll
    for (int i = 0; i < 3; i++) {
        float z = fmaf(T[i*4+0], r0, fmaf(T[i*4+1], r1, fmaf(T[i*4+2], r2, T[i*4+3])));
        g_trans[idx*3+i] = 1.0f / (1.0f + expf(-z));
    }
}

// ---------------- ego init: ego0[b][q][:] = x[q][off_b][:] ----------------
__global__ void ego_init_kernel(const float* __restrict__ x) {
    int idx = blockIdx.x * blockDim.x + threadIdx.x;   // over NB*QN*(EN/4)
    if (idx >= NB * QN * (EN/4)) return;
    int e4 = idx & 63;
    int rq = idx >> 6;
    int b  = rq >> 11;
    int q  = rq & (QN-1);
    int off = g_batch_off[b];
    float4 v = *(const float4*)(x + (size_t)q*(TOTC*EN) + off*EN + e4*4);
    *(float4*)(&g_ego[0][(size_t)rq*EN + e4*4]) = v;
}

// ---------------- GEMM1: hidden = relu(pe @ W1^T + b1), pe generated on the fly ----------------
__global__ __launch_bounds__(256) void gemm_bev1(const float* __restrict__ W1,
                                                 const float* __restrict__ b1) {
    const int bm = blockIdx.x, bn = blockIdx.y;
    const int cav = bm >> 4;                      // 2048/128 = 16 row-tiles per cav
    if (g_cav_local[cav] == 0 || g_batch_n[g_cav_batch[cav]] <= 1) return;

    __shared__ float As[16][132];
    __shared__ float Bs[16][132];
    __shared__ float fr[EN];
    __shared__ float tr[128][3];

    const int t  = threadIdx.x;
    const int tm = t >> 4, tn = t & 15;
    const int lr = t >> 2, lc4 = t & 3;
    const int m0 = bm * 128, n0 = bn * 128;

    fr[t] = g_freq[t & (EN-1)];
    for (int i = t; i < 128*3; i += 256)
        tr[i/3][i%3] = g_trans[(size_t)(m0 + i/3)*3 + (i%3)];

    float acc[8][8] = {};
    __syncthreads();

    for (int kt = 0; kt < 48; kt++) {
        const int k0 = kt * 16;
        const int d  = k0 >> 8;                   // which coordinate (0..2)
        #pragma unroll
        for (int rr = 0; rr < 2; rr++) {
            const int m = lr + rr * 64;
            const float tv = tr[m][d];
            #pragma unroll
            for (int i = 0; i < 4; i++) {
                const int kk = lc4 * 4 + i;
                const int j  = (k0 + kk) & 255;
                const float arg = tv * fr[j];
                As[kk][m] = (j & 1) ? __cosf(arg) : __sinf(arg);
            }
        }
        #pragma unroll
        for (int rr = 0; rr < 2; rr++) {
            const int nn = lr + rr * 64;
            const float4 v = *(const float4*)(W1 + (size_t)(n0 + nn)*768 + k0 + lc4*4);
            Bs[lc4*4+0][nn] = v.x; Bs[lc4*4+1][nn] = v.y;
            Bs[lc4*4+2][nn] = v.z; Bs[lc4*4+3][nn] = v.w;
        }
        __syncthreads();
        #pragma unroll
        for (int kk = 0; kk < 16; kk++) {
            float af[8], bf[8];
            *(float4*)&af[0] = *(const float4*)&As[kk][tm*8];
            *(float4*)&af[4] = *(const float4*)&As[kk][tm*8+4];
            *(float4*)&bf[0] = *(const float4*)&Bs[kk][tn*8];
            *(float4*)&bf[4] = *(const float4*)&Bs[kk][tn*8+4];
            #pragma unroll
            for (int i = 0; i < 8; i++)
                #pragma unroll
                for (int j = 0; j < 8; j++)
                    acc[i][j] = fmaf(af[i], bf[j], acc[i][j]);
        }
        __syncthreads();
    }
    #pragma unroll
    for (int i = 0; i < 8; i++) {
        int row = m0 + tm*8 + i;
        int nbase = n0 + tn*8;
        float v[8];
        #pragma unroll
        for (int j = 0; j < 8; j++) v[j] = fmaxf(acc[i][j] + b1[nbase + j], 0.0f);
        float* dst = g_hidden + (size_t)row*EN + nbase;
        *(float4*)(dst)   = make_float4(v[0], v[1], v[2], v[3]);
        *(float4*)(dst+4) = make_float4(v[4], v[5], v[6], v[7]);
    }
}

// ---------------- generic K=256,N=256 GEMM with fused epilogues ----------------
// MODE 0: kk  = x_row + hidden @ W2^T + b2          (neighbor cavs only)
// MODE 1: kp  = kk @ Wk^T + bk                      (neighbor cavs only)
// MODE 2: vp  = x_row @ Wv^T + bv                   (neighbor cavs only; A read from x, strided)
// MODE 3: qp  = ego[sel] @ Wq^T + bq                (batches with n>1)
// MODE 4: ego[sel^1] = (n-1) * (ego[sel] + ctx @ Wo^T + bo)
template<int MODE>
__global__ __launch_bounds__(256) void gemm256(const float* __restrict__ W,
                                               const float* __restrict__ bias,
                                               const float* __restrict__ X,
                                               int sel) {
    const int bm = blockIdx.x, bn = blockIdx.y;
    int cav = 0; float scale = 1.0f;
    if (MODE <= 2) {
        cav = bm >> 4;
        if (g_cav_local[cav] == 0 || g_batch_n[g_cav_batch[cav]] <= 1) return;
    } else {
        int batch = bm >> 4;
        int n = g_batch_n[batch];
        if (n <= 1) return;
        scale = (float)(n - 1);
    }
    const float* A;
    if      (MODE == 0) A = g_hidden;
    else if (MODE == 1) A = g_kk;
    else if (MODE == 2) A = X;                 // x, strided by query
    else if (MODE == 3) A = g_ego[sel & 1];
    else                A = g_ctx;

    __shared__ float As[16][132];
    __shared__ float Bs[16][132];
    const int t  = threadIdx.x;
    const int tm = t >> 4, tn = t & 15;
    const int lr = t >> 2, lc4 = t & 3;
    const int m0 = bm * 128, n0 = bn * 128;
    float acc[8][8] = {};

    for (int kt = 0; kt < 16; kt++) {
        const int k0 = kt * 16;
        #pragma unroll
        for (int rr = 0; rr < 2; rr++) {
            const int m = lr + rr * 64;
            const int row = m0 + m;
            const float* src;
            if (MODE == 2) {
                int q = row & (QN - 1);
                src = A + (size_t)q*(TOTC*EN) + cav*EN + k0 + lc4*4;
            } else {
                src = A + (size_t)row*EN + k0 + lc4*4;
            }
            float4 v = *(const float4*)src;
            As[lc4*4+0][m] = v.x; As[lc4*4+1][m] = v.y;
            As[lc4*4+2][m] = v.z; As[lc4*4+3][m] = v.w;
        }
        #pragma unroll
        for (int rr = 0; rr < 2; rr++) {
            const int nn = lr + rr * 64;
            const float4 v = *(const float4*)(W + (size_t)(n0 + nn)*EN + k0 + lc4*4);
            Bs[lc4*4+0][nn] = v.x; Bs[lc4*4+1][nn] = v.y;
            Bs[lc4*4+2][nn] = v.z; Bs[lc4*4+3][nn] = v.w;
        }
        __syncthreads();
        #pragma unroll
        for (int kk = 0; kk < 16; kk++) {
            float af[8], bf[8];
            *(float4*)&af[0] = *(const float4*)&As[kk][tm*8];
            *(float4*)&af[4] = *(const float4*)&As[kk][tm*8+4];
            *(float4*)&bf[0] = *(const float4*)&Bs[kk][tn*8];
            *(float4*)&bf[4] = *(const float4*)&Bs[kk][tn*8+4];
            #pragma unroll
            for (int i = 0; i < 8; i++)
                #pragma unroll
                for (int j = 0; j < 8; j++)
                    acc[i][j] = fmaf(af[i], bf[j], acc[i][j]);
        }
        __syncthreads();
    }
    #pragma unroll
    for (int i = 0; i < 8; i++) {
        const int row = m0 + tm*8 + i;
        const int nbase = n0 + tn*8;
        float v[8];
        #pragma unroll
        for (int j = 0; j < 8; j++) v[j] = acc[i][j] + bias[nbase + j];
        float* dst;
        if (MODE == 0) {
            int q = row & (QN - 1);
            const float* xr = X + (size_t)q*(TOTC*EN) + cav*EN + nbase;
            #pragma unroll
            for (int j = 0; j < 8; j++) v[j] += xr[j];
            dst = g_kk + (size_t)row*EN + nbase;
        } else if (MODE == 1) {
            dst = g_kp + (size_t)row*EN + nbase;
        } else if (MODE == 2) {
            dst = g_vp + (size_t)row*EN + nbase;
        } else if (MODE == 3) {
            dst = g_qp + (size_t)row*EN + nbase;
        } else {
            const float* er = g_ego[sel & 1] + (size_t)row*EN + nbase;
            #pragma unroll
            for (int j = 0; j < 8; j++) v[j] = scale * (er[j] + v[j]);
            dst = g_ego[(sel ^ 1) & 1] + (size_t)row*EN + nbase;
        }
        *(float4*)(dst)   = make_float4(v[0], v[1], v[2], v[3]);
        *(float4*)(dst+4) = make_float4(v[4], v[5], v[6], v[7]);
    }
}

// ---------------- degenerate attention: one warp per (b,q,h) ----------------
__global__ void attn_kernel() {
    int w = (blockIdx.x * blockDim.x + threadIdx.x) >> 5;
    int lane = threadIdx.x & 31;
    if (w >= NB * QN * NH) return;
    int h  = w & 7;
    int bq = w >> 3;
    int b  = bq >> 11;
    int q  = bq & (QN - 1);
    int n  = g_batch_n[b];
    if (n <= 1) return;
    int nm  = n - 1;
    int off = g_batch_off[b];
    int col = h * 32 + lane;

    float qv = g_qp[(size_t)bq*EN + col];
    float sc[LMAXC - 1];
    for (int m = 0; m < nm; m++) {
        int c = off + 1 + m;
        float p = qv * g_kp[(size_t)(c*QN + q)*EN + col];
        #pragma unroll
        for (int o = 16; o; o >>= 1) p += __shfl_xor_sync(0xffffffffu, p, o);
        sc[m] = p * 0.17677669529663687f;   // 1/sqrt(32)
    }
    float mx = -1e30f;
    for (int m = 0; m < nm; m++) mx = fmaxf(mx, sc[m]);
    float s = 0.0f, wt[LMAXC - 1];
    for (int m = 0; m < nm; m++) { wt[m] = __expf(sc[m] - mx); s += wt[m]; }
    float inv = 1.0f / s;
    float ctx = 0.0f;
    for (int m = 0; m < nm; m++) {
        int c = off + 1 + m;
        ctx = fmaf(wt[m] * inv, g_vp[(size_t)(c*QN + q)*EN + col], ctx);
    }
    g_ctx[(size_t)bq*EN + col] = ctx;
}

// ---------------- final: out = x, except ego rows of multi-cav batches ----------------
__global__ void out_kernel(const float* __restrict__ x, float* __restrict__ out, int fin) {
    int idx = blockIdx.x * blockDim.x + threadIdx.x;   // (q, c, e4)
    if (idx >= QN * TOTC * (EN/4)) return;
    int e4 = idx & 63;
    int qc = idx >> 6;
    int c  = qc % TOTC;
    int q  = qc / TOTC;
    int b  = g_cav_batch[c], l = g_cav_local[c];
    float4 v;
    if (l == 0 && g_batch_n[b] > 1)
        v = *(const float4*)(g_ego[fin & 1] + (size_t)(b*QN + q)*EN + e4*4);
    else
        v = *(const float4*)(x + (size_t)idx*4);
    *(float4*)(out + (size_t)idx*4) = v;
}

// ---------------- launch ----------------
extern "C" void kernel_launch(void* const* d_in, const int* in_sizes, int n_in,
                              void* d_out, int out_size) {
    const float*     x    = (const float*)d_in[0];
    const float*     rp   = (const float*)d_in[1];
    const float*     ptm  = (const float*)d_in[2];
    const long long* rl   = (const long long*)d_in[3];
    const float*     in_w = (const float*)d_in[4];
    const float*     in_b = (const float*)d_in[5];
    const float*     ow   = (const float*)d_in[6];
    const float*     ob   = (const float*)d_in[7];
    const float*     w1   = (const float*)d_in[8];
    const float*     b1   = (const float*)d_in[9];
    const float*     w2   = (const float*)d_in[10];
    const float*     b2   = (const float*)d_in[11];
    float* out = (float*)d_out;

    setup_kernel<<<1, 256>>>(rl);
    trans_kernel<<<(TOTC*QN + 255)/256, 256>>>(rp, ptm);
    ego_init_kernel<<<(NB*QN*(EN/4) + 255)/256, 256>>>(x);

    dim3 gcav(TOTC*QN/128, 2);
    gemm_bev1<<<gcav, 256>>>(w1, b1);
    gemm256<0><<<gcav, 256>>>(w2, b2, x, 0);                     // kk
    gemm256<1><<<gcav, 256>>>(in_w + 256*EN, in_b + 256, x, 0);  // kp
    gemm256<2><<<gcav, 256>>>(in_w + 512*EN, in_b + 512, x, 0);  // vp

    dim3 gego(NB*QN/128, 2);
    int cur = 0;
    for (int it = 0; it < 2; it++) {
        gemm256<3><<<gego, 256>>>(in_w, in_b, x, cur);           // qp
        attn_kernel<<<NB*QN*NH*32/256, 256>>>();                 // ctx
        gemm256<4><<<gego, 256>>>(ow, ob, x, cur);               // ego update
        cur ^= 1;
    }
    out_kernel<<<(QN*TOTC*(EN/4) + 255)/256, 256>>>(x, out, cur);
}

// round 3
// speedup vs baseline: 1.5128x; 1.5128x over previous
#include <cuda_runtime.h>

#define QN    2048
#define EN    256
#define TOTC  40
#define NB    8
#define LMAXC 5
#define NH    8
#define NTAB  2048

// ---------------- scratch (static device globals; no allocation) ----------------
__device__ float g_trans [TOTC*QN*3];
__device__ float g_hidden[TOTC*QN*EN];
__device__ float g_kp    [TOTC*QN*EN];
__device__ float g_vp    [TOTC*QN*EN];
__device__ float g_ego   [2][NB*QN*EN];
__device__ float g_qp    [NB*QN*EN];
__device__ float g_ctx   [NB*QN*EN];
__device__ float g_table [3*NTAB*EN];     // 6.3 MB, L2-resident
__device__ float g_wcat  [EN*512];        // [Wk | Wk@W2] per output row
__device__ float g_bkp   [EN];            // bk + Wk@b2
__device__ float g_freq  [EN];
__device__ int   g_cav_batch[TOTC];
__device__ int   g_cav_local[TOTC];
__device__ int   g_batch_n  [NB];
__device__ int   g_batch_off[NB];

// ---------------- setup ----------------
__global__ void setup_kernel(const long long* __restrict__ rl64) {
    int t = threadIdx.x;
    if (t == 0) {
        bool ok64 = true;
        for (int b = 0; b < NB; b++) {
            long long v = rl64[b];
            if (v < 1 || v > LMAXC) ok64 = false;
        }
        const int* rl32 = (const int*)rl64;
        int acc = 0;
        for (int c = 0; c < TOTC; c++) { g_cav_batch[c] = 0; g_cav_local[c] = 0; }
        for (int b = 0; b < NB; b++) {
            int n = ok64 ? (int)rl64[b] : rl32[b];
            if (n < 1) n = 1;
            if (n > LMAXC) n = LMAXC;
            g_batch_n[b] = n; g_batch_off[b] = acc;
            for (int l = 0; l < n; l++) {
                int c = acc + l;
                if (c < TOTC) { g_cav_batch[c] = b; g_cav_local[c] = l; }
            }
            acc += n;
        }
    }
    for (int j = t; j < EN; j += blockDim.x) {
        float ex = (2.0f * (float)(j >> 1)) / (float)EN;
        g_freq[j] = 6.283185307179586f * expf(-ex * 9.210340371976184f);
    }
}

// ---------------- trans = sigmoid(T @ homo)[:3] ----------------
__global__ void trans_kernel(const float* __restrict__ rp, const float* __restrict__ ptm) {
    int idx = blockIdx.x * blockDim.x + threadIdx.x;
    if (idx >= TOTC * QN) return;
    int c = idx / QN;
    int b = g_cav_batch[c], l = g_cav_local[c];
    float r0 = rp[idx*3+0] * 281.6f - 140.8f;
    float r1 = rp[idx*3+1] *  80.0f -  40.0f;
    float r2 = rp[idx*3+2] *   4.0f -   3.0f;
    const float* T = ptm + (size_t)((b * LMAXC + l) * LMAXC) * 16;
    #pragma unroll
    for (int i = 0; i < 3; i++) {
        float z = fmaf(T[i*4+0], r0, fmaf(T[i*4+1], r1, fmaf(T[i*4+2], r2, T[i*4+3])));
        g_trans[idx*3+i] = 1.0f / (1.0f + expf(-z));
    }
}

// ---------------- ego init ----------------
__global__ void ego_init_kernel(const float* __restrict__ x) {
    int idx = blockIdx.x * blockDim.x + threadIdx.x;
    if (idx >= NB * QN * (EN/4)) return;
    int e4 = idx & 63;
    int rq = idx >> 6;
    int b  = rq >> 11;
    int q  = rq & (QN-1);
    int off = g_batch_off[b];
    float4 v = *(const float4*)(x + (size_t)q*(TOTC*EN) + off*EN + e4*4);
    *(float4*)(&g_ego[0][(size_t)rq*EN + e4*4]) = v;
}

// ---------------- Wkk = Wk @ W2, wcat = [Wk | Wkk], bkp = bk + Wk@b2 ----------------
__global__ void wkk_kernel(const float* __restrict__ in_w, const float* __restrict__ in_b,
                           const float* __restrict__ w2,   const float* __restrict__ b2) {
    __shared__ float sWk[EN];
    int n = blockIdx.x, j = threadIdx.x;
    sWk[j] = in_w[(size_t)(EN + n)*EN + j];
    __syncthreads();
    float acc = 0.0f;
    for (int m = 0; m < EN; m++) acc = fmaf(sWk[m], w2[(size_t)m*EN + j], acc);
    g_wcat[(size_t)n*512 + j]      = sWk[j];
    g_wcat[(size_t)n*512 + EN + j] = acc;
    if (j == 0) {
        float b = in_b[EN + n];
        for (int m = 0; m < EN; m++) b = fmaf(sWk[m], b2[m], b);
        g_bkp[n] = b;
    }
}

// ---------------- table[d][i][n] = sum_j trig(t_i*f_j) * W1[n][d*256+j] ----------------
__global__ __launch_bounds__(256) void table_kernel(const float* __restrict__ W1) {
    const int bm = blockIdx.x, bn = blockIdx.y;
    const int d  = bm / (NTAB/128);
    const int ib = (bm % (NTAB/128)) * 128;
    __shared__ float As[16][132];
    __shared__ float Bs[16][132];
    __shared__ float fr[EN];
    const int t  = threadIdx.x;
    const int tm = t >> 4, tn = t & 15;
    const int lr = t >> 2, lc4 = t & 3;
    const int n0 = bn * 128;
    fr[t] = g_freq[t & (EN-1)];
    __syncthreads();
    float acc[8][8] = {};
    const float inv = 1.0f / (float)(NTAB - 1);
    for (int kt = 0; kt < 16; kt++) {
        const int k0 = kt * 16;
        #pragma unroll
        for (int rr = 0; rr < 2; rr++) {
            const int m = lr + rr * 64;
            const float tv = (float)(ib + m) * inv;
            #pragma unroll
            for (int i = 0; i < 4; i++) {
                const int kk = lc4*4 + i, j = k0 + kk;
                const float arg = tv * fr[j];
                As[kk][m] = (j & 1) ? __cosf(arg) : __sinf(arg);
            }
        }
        #pragma unroll
        for (int rr = 0; rr < 2; rr++) {
            const int nn = lr + rr * 64;
            const float4 v = *(const float4*)(W1 + (size_t)(n0+nn)*768 + d*256 + k0 + lc4*4);
            Bs[lc4*4+0][nn] = v.x; Bs[lc4*4+1][nn] = v.y;
            Bs[lc4*4+2][nn] = v.z; Bs[lc4*4+3][nn] = v.w;
        }
        __syncthreads();
        #pragma unroll
        for (int kk = 0; kk < 16; kk++) {
            float af[8], bf[8];
            *(float4*)&af[0] = *(const float4*)&As[kk][tm*8];
            *(float4*)&af[4] = *(const float4*)&As[kk][tm*8+4];
            *(float4*)&bf[0] = *(const float4*)&Bs[kk][tn*8];
            *(float4*)&bf[4] = *(const float4*)&Bs[kk][tn*8+4];
            #pragma unroll
            for (int i = 0; i < 8; i++)
                #pragma unroll
                for (int j = 0; j < 8; j++)
                    acc[i][j] = fmaf(af[i], bf[j], acc[i][j]);
        }
        __syncthreads();
    }
    #pragma unroll
    for (int i = 0; i < 8; i++) {
        const int row = ib + tm*8 + i;
        float* dst = g_table + ((size_t)(d*NTAB + row))*EN + n0 + tn*8;
        *(float4*)(dst)   = make_float4(acc[i][0], acc[i][1], acc[i][2], acc[i][3]);
        *(float4*)(dst+4) = make_float4(acc[i][4], acc[i][5], acc[i][6], acc[i][7]);
    }
}

// ---------------- hidden = relu(b1 + sum_d lerp(table_d, t_d)) ----------------
__global__ void bev_lookup(const float* __restrict__ b1) {
    int idx = blockIdx.x * blockDim.x + threadIdx.x;
    if (idx >= TOTC*QN*(EN/4)) return;
    int n4  = idx & 63;
    int row = idx >> 6;
    int cav = row >> 11;
    if (g_cav_local[cav] == 0 || g_batch_n[g_cav_batch[cav]] <= 1) return;
    float4 acc = *(const float4*)(b1 + n4*4);
    #pragma unroll
    for (int d = 0; d < 3; d++) {
        float tv = g_trans[(size_t)row*3 + d];
        float u  = tv * (float)(NTAB - 1);
        int i0 = (int)u;
        if (i0 < 0) i0 = 0;
        if (i0 > NTAB-2) i0 = NTAB-2;
        float w = u - (float)i0;
        const float* r = g_table + ((size_t)(d*NTAB + i0))*EN + n4*4;
        float4 a = *(const float4*)r;
        float4 b = *(const float4*)(r + EN);
        acc.x = fmaf(w, b.x - a.x, acc.x + a.x);
        acc.y = fmaf(w, b.y - a.y, acc.y + a.y);
        acc.z = fmaf(w, b.z - a.z, acc.z + a.z);
        acc.w = fmaf(w, b.w - a.w, acc.w + a.w);
    }
    float4 o = make_float4(fmaxf(acc.x,0.f), fmaxf(acc.y,0.f), fmaxf(acc.z,0.f), fmaxf(acc.w,0.f));
    *(float4*)(g_hidden + (size_t)row*EN + n4*4) = o;
}

// ---------------- double-buffered GEMM, fused epilogues ----------------
// MODE 1: kp = [x_row | hidden] @ wcat^T + bkp   (K=512, neighbor cavs)
// MODE 2: vp = x_row @ Wv^T + bv                 (K=256, neighbor cavs)
// MODE 3: qp = ego[sel] @ Wq^T + bq              (K=256, multi batches)
// MODE 4: ego[sel^1] = (n-1)*(ego[sel] + ctx @ Wo^T + bo)
#define AS(buf,kk,m) sm[((buf)*16+(kk))*132 + (m)]
#define BS(buf,kk,m) sm[8448 + ((buf)*16+(kk))*132 + (m)]

template<int MODE, int KT>
__global__ __launch_bounds__(256, 2) void dgemm(const float* __restrict__ W,
                                                const float* __restrict__ bias,
                                                const float* __restrict__ X,
                                                int sel) {
    extern __shared__ float sm[];
    const int bm = blockIdx.x, bn = blockIdx.y;
    int cav = 0; float scale = 1.0f;
    if (MODE == 1 || MODE == 2) {
        cav = bm >> 4;
        if (g_cav_local[cav] == 0 || g_batch_n[g_cav_batch[cav]] <= 1) return;
    } else {
        int batch = bm >> 4;
        int n = g_batch_n[batch];
        if (n <= 1) return;
        scale = (float)(n - 1);
    }
    const int t  = threadIdx.x;
    const int tm = t >> 4, tn = t & 15;
    const int lr = t >> 2, lc4 = t & 3;
    const int m0 = bm * 128, n0 = bn * 128;

    float4 pa[2], pb[2];

    auto ld = [&](int kt) {
        const int k0 = kt*16 + lc4*4;
        #pragma unroll
        for (int rr = 0; rr < 2; rr++) {
            const int row = m0 + lr + rr*64;
            const float* s;
            if (MODE == 1) {
                if (k0 < 256) { int q = row & (QN-1); s = X + (size_t)q*(TOTC*EN) + cav*EN + k0; }
                else           s = g_hidden + (size_t)row*EN + (k0 - 256);
            } else if (MODE == 2) {
                int q = row & (QN-1); s = X + (size_t)q*(TOTC*EN) + cav*EN + k0;
            } else if (MODE == 3) {
                s = g_ego[sel & 1] + (size_t)row*EN + k0;
            } else {
                s = g_ctx + (size_t)row*EN + k0;
            }
            pa[rr] = *(const float4*)s;
            const float* wsrc = (MODE == 1)
                ? (g_wcat + (size_t)(n0 + lr + rr*64)*512 + k0)
                : (W      + (size_t)(n0 + lr + rr*64)*EN  + k0);
            pb[rr] = *(const float4*)wsrc;
        }
    };
    auto st = [&](int buf) {
        #pragma unroll
        for (int rr = 0; rr < 2; rr++) {
            const int m = lr + rr*64;
            AS(buf, lc4*4+0, m) = pa[rr].x; AS(buf, lc4*4+1, m) = pa[rr].y;
            AS(buf, lc4*4+2, m) = pa[rr].z; AS(buf, lc4*4+3, m) = pa[rr].w;
            BS(buf, lc4*4+0, m) = pb[rr].x; BS(buf, lc4*4+1, m) = pb[rr].y;
            BS(buf, lc4*4+2, m) = pb[rr].z; BS(buf, lc4*4+3, m) = pb[rr].w;
        }
    };

    float acc[8][8] = {};
    ld(0); st(0);
    __syncthreads();
    for (int kt = 0; kt < KT; kt++) {
        if (kt + 1 < KT) ld(kt + 1);
        const int buf = kt & 1;
        #pragma unroll
        for (int kk = 0; kk < 16; kk++) {
            float af[8], bf[8];
            *(float4*)&af[0] = *(const float4*)&AS(buf, kk, tm*8);
            *(float4*)&af[4] = *(const float4*)&AS(buf, kk, tm*8+4);
            *(float4*)&bf[0] = *(const float4*)&BS(buf, kk, tn*8);
            *(float4*)&bf[4] = *(const float4*)&BS(buf, kk, tn*8+4);
            #pragma unroll
            for (int i = 0; i < 8; i++)
                #pragma unroll
                for (int j = 0; j < 8; j++)
                    acc[i][j] = fmaf(af[i], bf[j], acc[i][j]);
        }
        if (kt + 1 < KT) st(buf ^ 1);
        __syncthreads();
    }
    #pragma unroll
    for (int i = 0; i < 8; i++) {
        const int row = m0 + tm*8 + i;
        const int nb  = n0 + tn*8;
        float v[8];
        #pragma unroll
        for (int j = 0; j < 8; j++)
            v[j] = acc[i][j] + ((MODE == 1) ? g_bkp[nb + j] : bias[nb + j]);
        float* dst;
        if (MODE == 1)      dst = g_kp + (size_t)row*EN + nb;
        else if (MODE == 2) dst = g_vp + (size_t)row*EN + nb;
        else if (MODE == 3) dst = g_qp + (size_t)row*EN + nb;
        else {
            const float* er = g_ego[sel & 1] + (size_t)row*EN + nb;
            #pragma unroll
            for (int j = 0; j < 8; j++) v[j] = scale * (er[j] + v[j]);
            dst = g_ego[(sel ^ 1) & 1] + (size_t)row*EN + nb;
        }
        *(float4*)(dst)   = make_float4(v[0], v[1], v[2], v[3]);
        *(float4*)(dst+4) = make_float4(v[4], v[5], v[6], v[7]);
    }
}

// ---------------- degenerate attention: one warp per (b,q,h) ----------------
__global__ void attn_kernel() {
    int w = (blockIdx.x * blockDim.x + threadIdx.x) >> 5;
    int lane = threadIdx.x & 31;
    if (w >= NB * QN * NH) return;
    int h  = w & 7;
    int bq = w >> 3;
    int b  = bq >> 11;
    int q  = bq & (QN - 1);
    int n  = g_batch_n[b];
    if (n <= 1) return;
    int nm  = n - 1;
    int off = g_batch_off[b];
    int col = h * 32 + lane;

    float qv = g_qp[(size_t)bq*EN + col];
    float sc[LMAXC - 1];
    for (int m = 0; m < nm; m++) {
        int c = off + 1 + m;
        float p = qv * g_kp[(size_t)(c*QN + q)*EN + col];
        #pragma unroll
        for (int o = 16; o; o >>= 1) p += __shfl_xor_sync(0xffffffffu, p, o);
        sc[m] = p * 0.17677669529663687f;
    }
    float mx = -1e30f;
    for (int m = 0; m < nm; m++) mx = fmaxf(mx, sc[m]);
    float s = 0.0f, wt[LMAXC - 1];
    for (int m = 0; m < nm; m++) { wt[m] = __expf(sc[m] - mx); s += wt[m]; }
    float inv = 1.0f / s;
    float ctx = 0.0f;
    for (int m = 0; m < nm; m++) {
        int c = off + 1 + m;
        ctx = fmaf(wt[m] * inv, g_vp[(size_t)(c*QN + q)*EN + col], ctx);
    }
    g_ctx[(size_t)bq*EN + col] = ctx;
}

// ---------------- final merge ----------------
__global__ void out_kernel(const float* __restrict__ x, float* __restrict__ out, int fin) {
    int idx = blockIdx.x * blockDim.x + threadIdx.x;
    if (idx >= QN * TOTC * (EN/4)) return;
    int e4 = idx & 63;
    int qc = idx >> 6;
    int c  = qc % TOTC;
    int q  = qc / TOTC;
    int b  = g_cav_batch[c], l = g_cav_local[c];
    float4 v;
    if (l == 0 && g_batch_n[b] > 1)
        v = *(const float4*)(g_ego[fin & 1] + (size_t)(b*QN + q)*EN + e4*4);
    else
        v = *(const float4*)(x + (size_t)idx*4);
    *(float4*)(out + (size_t)idx*4) = v;
}

// ---------------- launch ----------------
static const int DG_SMEM = 2 * 8448 * (int)sizeof(float);   // 67584 B

extern "C" void kernel_launch(void* const* d_in, const int* in_sizes, int n_in,
                              void* d_out, int out_size) {
    const float*     x    = (const float*)d_in[0];
    const float*     rp   = (const float*)d_in[1];
    const float*     ptm  = (const float*)d_in[2];
    const long long* rl   = (const long long*)d_in[3];
    const float*     in_w = (const float*)d_in[4];
    const float*     in_b = (const float*)d_in[5];
    const float*     ow   = (const float*)d_in[6];
    const float*     ob   = (const float*)d_in[7];
    const float*     w1   = (const float*)d_in[8];
    const float*     b1   = (const float*)d_in[9];
    const float*     w2   = (const float*)d_in[10];
    const float*     b2   = (const float*)d_in[11];
    float* out = (float*)d_out;

    static bool attr_done = false;
    if (!attr_done) {
        cudaFuncSetAttribute(dgemm<1,32>, cudaFuncAttributeMaxDynamicSharedMemorySize, DG_SMEM);
        cudaFuncSetAttribute(dgemm<2,16>, cudaFuncAttributeMaxDynamicSharedMemorySize, DG_SMEM);
        cudaFuncSetAttribute(dgemm<3,16>, cudaFuncAttributeMaxDynamicSharedMemorySize, DG_SMEM);
        cudaFuncSetAttribute(dgemm<4,16>, cudaFuncAttributeMaxDynamicSharedMemorySize, DG_SMEM);
        attr_done = true;
    }

    setup_kernel<<<1, 256>>>(rl);
    trans_kernel<<<(TOTC*QN + 255)/256, 256>>>(rp, ptm);
    ego_init_kernel<<<(NB*QN*(EN/4) + 255)/256, 256>>>(x);
    wkk_kernel<<<EN, EN>>>(in_w, in_b, w2, b2);
    table_kernel<<<dim3(3*NTAB/128, 2), 256>>>(w1);
    bev_lookup<<<(TOTC*QN*(EN/4) + 255)/256, 256>>>(b1);

    dim3 gcav(TOTC*QN/128, 2);
    dgemm<1,32><<<gcav, 256, DG_SMEM>>>(nullptr,        nullptr,      x, 0);   // kp
    dgemm<2,16><<<gcav, 256, DG_SMEM>>>(in_w + 512*EN,  in_b + 512,   x, 0);   // vp

    dim3 gego(NB*QN/128, 2);
    int cur = 0;
    for (int it = 0; it < 2; it++) {
        dgemm<3,16><<<gego, 256, DG_SMEM>>>(in_w, in_b, x, cur);               // qp
        attn_kernel<<<NB*QN*NH*32/256, 256>>>();                               // ctx
        dgemm<4,16><<<gego, 256, DG_SMEM>>>(ow, ob, x, cur);                   // ego
        cur ^= 1;
    }
    out_kernel<<<(QN*TOTC*(EN/4) + 255)/256, 256>>>(x, out, cur);
}

// round 4
// speedup vs baseline: 2.5562x; 1.6897x over previous
#include <cuda_runtime.h>
#include <cuda_bf16.h>
#include <cstdint>

#define QN    2048
#define EN    256
#define TOTC  40
#define NB    8
#define LMAXC 5
#define NH    8
#define NTAB  2048

// ---------------- scratch ----------------
__device__ float g_trans [TOTC*QN*3];
__device__ float g_hidden[TOTC*QN*EN];
__device__ float g_kp    [TOTC*QN*EN];
__device__ float g_vp    [TOTC*QN*EN];
__device__ float g_ego   [2][NB*QN*EN];
__device__ float g_qp    [NB*QN*EN];
__device__ float g_ctx   [NB*QN*EN];
__device__ float g_table [3*NTAB*EN];
__device__ float g_wcat  [EN*512];
__device__ float g_bkp   [EN];
__device__ float g_freq  [EN];
__device__ int   g_cav_batch[TOTC];
__device__ int   g_cav_local[TOTC];
__device__ int   g_batch_n  [NB];
__device__ int   g_batch_off[NB];

// ---------------- setup ----------------
__global__ void setup_kernel(const long long* __restrict__ rl64) {
    int t = threadIdx.x;
    if (t == 0) {
        bool ok64 = true;
        for (int b = 0; b < NB; b++) {
            long long v = rl64[b];
            if (v < 1 || v > LMAXC) ok64 = false;
        }
        const int* rl32 = (const int*)rl64;
        int acc = 0;
        for (int c = 0; c < TOTC; c++) { g_cav_batch[c] = 0; g_cav_local[c] = 0; }
        for (int b = 0; b < NB; b++) {
            int n = ok64 ? (int)rl64[b] : rl32[b];
            if (n < 1) n = 1;
            if (n > LMAXC) n = LMAXC;
            g_batch_n[b] = n; g_batch_off[b] = acc;
            for (int l = 0; l < n; l++) {
                int c = acc + l;
                if (c < TOTC) { g_cav_batch[c] = b; g_cav_local[c] = l; }
            }
            acc += n;
        }
    }
    for (int j = t; j < EN; j += blockDim.x) {
        float ex = (2.0f * (float)(j >> 1)) / (float)EN;
        g_freq[j] = 6.283185307179586f * expf(-ex * 9.210340371976184f);
    }
}

// ---------------- trans ----------------
__global__ void trans_kernel(const float* __restrict__ rp, const float* __restrict__ ptm) {
    int idx = blockIdx.x * blockDim.x + threadIdx.x;
    if (idx >= TOTC * QN) return;
    int c = idx / QN;
    int b = g_cav_batch[c], l = g_cav_local[c];
    float r0 = rp[idx*3+0] * 281.6f - 140.8f;
    float r1 = rp[idx*3+1] *  80.0f -  40.0f;
    float r2 = rp[idx*3+2] *   4.0f -   3.0f;
    const float* T = ptm + (size_t)((b * LMAXC + l) * LMAXC) * 16;
    #pragma unroll
    for (int i = 0; i < 3; i++) {
        float z = fmaf(T[i*4+0], r0, fmaf(T[i*4+1], r1, fmaf(T[i*4+2], r2, T[i*4+3])));
        g_trans[idx*3+i] = 1.0f / (1.0f + expf(-z));
    }
}

// ---------------- ego init ----------------
__global__ void ego_init_kernel(const float* __restrict__ x) {
    int idx = blockIdx.x * blockDim.x + threadIdx.x;
    if (idx >= NB * QN * (EN/4)) return;
    int e4 = idx & 63;
    int rq = idx >> 6;
    int b  = rq >> 11;
    int q  = rq & (QN-1);
    int off = g_batch_off[b];
    float4 v = *(const float4*)(x + (size_t)q*(TOTC*EN) + off*EN + e4*4);
    *(float4*)(&g_ego[0][(size_t)rq*EN + e4*4]) = v;
}

// ---------------- wcat = [Wk | Wk@W2], bkp = bk + Wk@b2 ----------------
__global__ void wkk_kernel(const float* __restrict__ in_w, const float* __restrict__ in_b,
                           const float* __restrict__ w2,   const float* __restrict__ b2) {
    __shared__ float sWk[EN];
    int n = blockIdx.x, j = threadIdx.x;
    sWk[j] = in_w[(size_t)(EN + n)*EN + j];
    __syncthreads();
    float acc = 0.0f;
    #pragma unroll 8
    for (int m = 0; m < EN; m++) acc = fmaf(sWk[m], w2[(size_t)m*EN + j], acc);
    g_wcat[(size_t)n*512 + j]      = sWk[j];
    g_wcat[(size_t)n*512 + EN + j] = acc;
    if (j == 0) {
        float b = in_b[EN + n];
        #pragma unroll 8
        for (int m = 0; m < EN; m++) b = fmaf(sWk[m], b2[m], b);
        g_bkp[n] = b;
    }
}

// ---------------- table GEMM (fp32 SIMT, small) ----------------
__global__ __launch_bounds__(256) void table_kernel(const float* __restrict__ W1) {
    const int bm = blockIdx.x, bn = blockIdx.y;
    const int d  = bm / (NTAB/128);
    const int ib = (bm % (NTAB/128)) * 128;
    __shared__ float As[16][132];
    __shared__ float Bs[16][132];
    __shared__ float fr[EN];
    const int t  = threadIdx.x;
    const int tm = t >> 4, tn = t & 15;
    const int lr = t >> 2, lc4 = t & 3;
    const int n0 = bn * 128;
    fr[t] = g_freq[t & (EN-1)];
    __syncthreads();
    float acc[8][8] = {};
    const float inv = 1.0f / (float)(NTAB - 1);
    for (int kt = 0; kt < 16; kt++) {
        const int k0 = kt * 16;
        #pragma unroll
        for (int rr = 0; rr < 2; rr++) {
            const int m = lr + rr * 64;
            const float tv = (float)(ib + m) * inv;
            #pragma unroll
            for (int i = 0; i < 4; i++) {
                const int kk = lc4*4 + i, j = k0 + kk;
                const float arg = tv * fr[j];
                As[kk][m] = (j & 1) ? __cosf(arg) : __sinf(arg);
            }
        }
        #pragma unroll
        for (int rr = 0; rr < 2; rr++) {
            const int nn = lr + rr * 64;
            const float4 v = *(const float4*)(W1 + (size_t)(n0+nn)*768 + d*256 + k0 + lc4*4);
            Bs[lc4*4+0][nn] = v.x; Bs[lc4*4+1][nn] = v.y;
            Bs[lc4*4+2][nn] = v.z; Bs[lc4*4+3][nn] = v.w;
        }
        __syncthreads();
        #pragma unroll
        for (int kk = 0; kk < 16; kk++) {
            float af[8], bf[8];
            *(float4*)&af[0] = *(const float4*)&As[kk][tm*8];
            *(float4*)&af[4] = *(const float4*)&As[kk][tm*8+4];
            *(float4*)&bf[0] = *(const float4*)&Bs[kk][tn*8];
            *(float4*)&bf[4] = *(const float4*)&Bs[kk][tn*8+4];
            #pragma unroll
            for (int i = 0; i < 8; i++)
                #pragma unroll
                for (int j = 0; j < 8; j++)
                    acc[i][j] = fmaf(af[i], bf[j], acc[i][j]);
        }
        __syncthreads();
    }
    #pragma unroll
    for (int i = 0; i < 8; i++) {
        const int row = ib + tm*8 + i;
        float* dst = g_table + ((size_t)(d*NTAB + row))*EN + n0 + tn*8;
        *(float4*)(dst)   = make_float4(acc[i][0], acc[i][1], acc[i][2], acc[i][3]);
        *(float4*)(dst+4) = make_float4(acc[i][4], acc[i][5], acc[i][6], acc[i][7]);
    }
}

// ---------------- hidden = relu(b1 + sum_d lerp(table_d, t_d)) ----------------
__global__ void bev_lookup(const float* __restrict__ b1) {
    int idx = blockIdx.x * blockDim.x + threadIdx.x;
    if (idx >= TOTC*QN*(EN/4)) return;
    int n4  = idx & 63;
    int row = idx >> 6;
    int cav = row >> 11;
    if (g_cav_local[cav] == 0 || g_batch_n[g_cav_batch[cav]] <= 1) return;
    float4 acc = *(const float4*)(b1 + n4*4);
    #pragma unroll
    for (int d = 0; d < 3; d++) {
        float tv = g_trans[(size_t)row*3 + d];
        float u  = tv * (float)(NTAB - 1);
        int i0 = (int)u;
        if (i0 < 0) i0 = 0;
        if (i0 > NTAB-2) i0 = NTAB-2;
        float w = u - (float)i0;
        const float* r = g_table + ((size_t)(d*NTAB + i0))*EN + n4*4;
        float4 a = *(const float4*)r;
        float4 b = *(const float4*)(r + EN);
        acc.x = fmaf(w, b.x - a.x, acc.x + a.x);
        acc.y = fmaf(w, b.y - a.y, acc.y + a.y);
        acc.z = fmaf(w, b.z - a.z, acc.z + a.z);
        acc.w = fmaf(w, b.w - a.w, acc.w + a.w);
    }
    float4 o = make_float4(fmaxf(acc.x,0.f), fmaxf(acc.y,0.f), fmaxf(acc.z,0.f), fmaxf(acc.w,0.f));
    *(float4*)(g_hidden + (size_t)row*EN + n4*4) = o;
}

// ================= bf16-split tensor-core GEMM =================
// C[m,n] = sum_k A[m,k] * W[n,k], with A,W split to (hi+lo) bf16 on the fly.
// 3 products: hi*whi + lo*whi + hi*wlo  (error ~1e-5, lo*wlo negligible)
// MODE 1: kp = [x|hidden] @ wcat^T + bkp   (K=512)
// MODE 2: vp = x @ Wv^T + bv
// MODE 3: qp = ego[sel] @ Wq^T + bq
// MODE 4: ego[sel^1] = (n-1)*(ego[sel] + ctx @ Wo^T + bo)

__device__ __forceinline__ uint32_t s2u(const void* p) {
    uint32_t a;
    asm("{ .reg .u64 t; cvta.to.shared.u64 t, %1; cvt.u32.u64 %0, t; }" : "=r"(a) : "l"(p));
    return a;
}
__device__ __forceinline__ void ldm4(uint32_t* f, uint32_t addr) {
    asm volatile("ldmatrix.sync.aligned.m8n8.x4.shared.b16 {%0,%1,%2,%3}, [%4];"
        : "=r"(f[0]),"=r"(f[1]),"=r"(f[2]),"=r"(f[3]) : "r"(addr));
}
__device__ __forceinline__ void mmabf(float* c, const uint32_t* a, const uint32_t* b) {
    asm volatile("mma.sync.aligned.m16n8k16.row.col.f32.bf16.bf16.f32 "
        "{%0,%1,%2,%3}, {%4,%5,%6,%7}, {%8,%9}, {%0,%1,%2,%3};"
        : "+f"(c[0]),"+f"(c[1]),"+f"(c[2]),"+f"(c[3])
        : "r"(a[0]),"r"(a[1]),"r"(a[2]),"r"(a[3]), "r"(b[0]),"r"(b[1]));
}
__device__ __forceinline__ uint32_t pkbf(float a, float b) {
    __nv_bfloat162 t = __floats2bfloat162_rn(a, b);
    return *(uint32_t*)&t;
}

#define TSTR 24              // smem row stride in halves (conflict-free ldmatrix)
#define TSZ  (128*TSTR)      // halves per tile

template<int MODE, int KT>
__global__ __launch_bounds__(256) void mma_gemm(const float* __restrict__ W,
                                                const float* __restrict__ bias,
                                                const float* __restrict__ X,
                                                int sel) {
    __shared__ __align__(16) __nv_bfloat16 sm[2*4*TSZ];   // [stage][ahi,alo,whi,wlo]

    const int bm = blockIdx.x, bn = blockIdx.y;
    int cav = 0; float scale = 1.0f;
    if (MODE == 1 || MODE == 2) {
        cav = bm >> 4;
        if (g_cav_local[cav] == 0 || g_batch_n[g_cav_batch[cav]] <= 1) return;
    } else {
        int batch = bm >> 4;
        int n = g_batch_n[batch];
        if (n <= 1) return;
        scale = (float)(n - 1);
    }
    const int t    = threadIdx.x;
    const int lane = t & 31, wid = t >> 5;
    const int wm   = wid & 3, wn = wid >> 2;
    const int m0   = bm * 128, n0 = bn * 128;

    // global-load indices (each thread: one row, 8 k-floats)
    const int lrow = t >> 1;           // 0..127
    const int lk   = (t & 1) * 8;      // 0 or 8

    // ldmatrix element offsets
    const int aoff = (wm*32 + (lane & 7) + ((lane >> 3) & 1) * 8) * TSTR + (lane >> 4) * 8;
    const int boff = (wn*64 + (lane & 7) + (lane >> 4) * 8) * TSTR + ((lane >> 3) & 1) * 8;

    const uint32_t smb = s2u(sm);

    float4 va0, va1, vw0, vw1;
    auto ld = [&](int kt) {
        const int k0 = kt * 16 + lk;
        const int arow = m0 + lrow;
        const float* s;
        if (MODE == 1) {
            if (k0 < 256) { int q = arow & (QN-1); s = X + (size_t)q*(TOTC*EN) + cav*EN + k0; }
            else            s = g_hidden + (size_t)arow*EN + (k0 - 256);
        } else if (MODE == 2) {
            int q = arow & (QN-1); s = X + (size_t)q*(TOTC*EN) + cav*EN + k0;
        } else if (MODE == 3) {
            s = g_ego[sel & 1] + (size_t)arow*EN + k0;
        } else {
            s = g_ctx + (size_t)arow*EN + k0;
        }
        va0 = *(const float4*)s;  va1 = *(const float4*)(s + 4);
        const float* ws = (MODE == 1) ? (g_wcat + (size_t)(n0 + lrow)*512 + k0)
                                      : (W      + (size_t)(n0 + lrow)*EN  + k0);
        vw0 = *(const float4*)ws; vw1 = *(const float4*)(ws + 4);
    };
    auto st = [&](int stage) {
        float a[8] = {va0.x,va0.y,va0.z,va0.w, va1.x,va1.y,va1.z,va1.w};
        float w[8] = {vw0.x,vw0.y,vw0.z,vw0.w, vw1.x,vw1.y,vw1.z,vw1.w};
        float ah[8], wh[8];
        uint32_t hi[4], lo[4];
        #pragma unroll
        for (int i = 0; i < 8; i++) ah[i] = __bfloat162float(__float2bfloat16_rn(a[i]));
        #pragma unroll
        for (int i = 0; i < 4; i++) {
            hi[i] = pkbf(ah[2*i], ah[2*i+1]);
            lo[i] = pkbf(a[2*i] - ah[2*i], a[2*i+1] - ah[2*i+1]);
        }
        const int eo = lrow * TSTR + lk;
        *(uint4*)&sm[(stage*4+0)*TSZ + eo] = make_uint4(hi[0],hi[1],hi[2],hi[3]);
        *(uint4*)&sm[(stage*4+1)*TSZ + eo] = make_uint4(lo[0],lo[1],lo[2],lo[3]);
        #pragma unroll
        for (int i = 0; i < 8; i++) wh[i] = __bfloat162float(__float2bfloat16_rn(w[i]));
        #pragma unroll
        for (int i = 0; i < 4; i++) {
            hi[i] = pkbf(wh[2*i], wh[2*i+1]);
            lo[i] = pkbf(w[2*i] - wh[2*i], w[2*i+1] - wh[2*i+1]);
        }
        *(uint4*)&sm[(stage*4+2)*TSZ + eo] = make_uint4(hi[0],hi[1],hi[2],hi[3]);
        *(uint4*)&sm[(stage*4+3)*TSZ + eo] = make_uint4(lo[0],lo[1],lo[2],lo[3]);
    };

    float acc[2][8][4] = {};

    ld(0); st(0);
    __syncthreads();
    for (int kt = 0; kt < KT; kt++) {
        if (kt + 1 < KT) ld(kt + 1);
        const int stage = kt & 1;
        const uint32_t bA = smb + (stage*4+0)*TSZ*2 + aoff*2;
        const uint32_t bAl= smb + (stage*4+1)*TSZ*2 + aoff*2;
        const uint32_t bW = smb + (stage*4+2)*TSZ*2 + boff*2;
        const uint32_t bWl= smb + (stage*4+3)*TSZ*2 + boff*2;

        uint32_t Ahi[2][4], Alo[2][4];
        #pragma unroll
        for (int ms = 0; ms < 2; ms++) {
            ldm4(Ahi[ms], bA  + ms*16*TSTR*2);
            ldm4(Alo[ms], bAl + ms*16*TSTR*2);
        }
        #pragma unroll
        for (int np = 0; np < 4; np++) {
            uint32_t Bhi[4], Blo[4];
            ldm4(Bhi, bW  + np*16*TSTR*2);
            ldm4(Blo, bWl + np*16*TSTR*2);
            #pragma unroll
            for (int ms = 0; ms < 2; ms++) {
                mmabf(acc[ms][2*np],   Ahi[ms], Bhi);
                mmabf(acc[ms][2*np+1], Ahi[ms], Bhi+2);
                mmabf(acc[ms][2*np],   Alo[ms], Bhi);
                mmabf(acc[ms][2*np+1], Alo[ms], Bhi+2);
                mmabf(acc[ms][2*np],   Ahi[ms], Blo);
                mmabf(acc[ms][2*np+1], Ahi[ms], Blo+2);
            }
        }
        if (kt + 1 < KT) st(stage ^ 1);
        __syncthreads();
    }

    // epilogue
    const float* bptr = (MODE == 1) ? g_bkp : bias;
    #pragma unroll
    for (int ms = 0; ms < 2; ms++) {
        const int row = m0 + wm*32 + ms*16 + (lane >> 2);
        #pragma unroll
        for (int ns = 0; ns < 8; ns++) {
            const int col = n0 + wn*64 + ns*8 + (lane & 3)*2;
            const float2 bv = *(const float2*)(bptr + col);
            #pragma unroll
            for (int h = 0; h < 2; h++) {          // h=0: row, h=1: row+8
                const int r = row + h*8;
                float v0 = acc[ms][ns][2*h]   + bv.x;
                float v1 = acc[ms][ns][2*h+1] + bv.y;
                float* dst;
                if (MODE == 1)      dst = g_kp + (size_t)r*EN + col;
                else if (MODE == 2) dst = g_vp + (size_t)r*EN + col;
                else if (MODE == 3) dst = g_qp + (size_t)r*EN + col;
                else {
                    const float2 er = *(const float2*)(g_ego[sel & 1] + (size_t)r*EN + col);
                    v0 = scale * (er.x + v0);
                    v1 = scale * (er.y + v1);
                    dst = g_ego[(sel ^ 1) & 1] + (size_t)r*EN + col;
                }
                *(float2*)dst = make_float2(v0, v1);
            }
        }
    }
}

// ---------------- degenerate attention ----------------
__global__ void attn_kernel() {
    int w = (blockIdx.x * blockDim.x + threadIdx.x) >> 5;
    int lane = threadIdx.x & 31;
    if (w >= NB * QN * NH) return;
    int h  = w & 7;
    int bq = w >> 3;
    int b  = bq >> 11;
    int q  = bq & (QN - 1);
    int n  = g_batch_n[b];
    if (n <= 1) return;
    int nm  = n - 1;
    int off = g_batch_off[b];
    int col = h * 32 + lane;

    float qv = g_qp[(size_t)bq*EN + col];
    float sc[LMAXC - 1];
    for (int m = 0; m < nm; m++) {
        int c = off + 1 + m;
        float p = qv * g_kp[(size_t)(c*QN + q)*EN + col];
        #pragma unroll
        for (int o = 16; o; o >>= 1) p += __shfl_xor_sync(0xffffffffu, p, o);
        sc[m] = p * 0.17677669529663687f;
    }
    float mx = -1e30f;
    for (int m = 0; m < nm; m++) mx = fmaxf(mx, sc[m]);
    float s = 0.0f, wt[LMAXC - 1];
    for (int m = 0; m < nm; m++) { wt[m] = __expf(sc[m] - mx); s += wt[m]; }
    float inv = 1.0f / s;
    float ctx = 0.0f;
    for (int m = 0; m < nm; m++) {
        int c = off + 1 + m;
        ctx = fmaf(wt[m] * inv, g_vp[(size_t)(c*QN + q)*EN + col], ctx);
    }
    g_ctx[(size_t)bq*EN + col] = ctx;
}

// ---------------- final merge ----------------
__global__ void out_kernel(const float* __restrict__ x, float* __restrict__ out, int fin) {
    int idx = blockIdx.x * blockDim.x + threadIdx.x;
    if (idx >= QN * TOTC * (EN/4)) return;
    int e4 = idx & 63;
    int qc = idx >> 6;
    int c  = qc % TOTC;
    int q  = qc / TOTC;
    int b  = g_cav_batch[c], l = g_cav_local[c];
    float4 v;
    if (l == 0 && g_batch_n[b] > 1)
        v = *(const float4*)(g_ego[fin & 1] + (size_t)(b*QN + q)*EN + e4*4);
    else
        v = *(const float4*)(x + (size_t)idx*4);
    *(float4*)(out + (size_t)idx*4) = v;
}

// ---------------- launch ----------------
extern "C" void kernel_launch(void* const* d_in, const int* in_sizes, int n_in,
                              void* d_out, int out_size) {
    const float*     x    = (const float*)d_in[0];
    const float*     rp   = (const float*)d_in[1];
    const float*     ptm  = (const float*)d_in[2];
    const long long* rl   = (const long long*)d_in[3];
    const float*     in_w = (const float*)d_in[4];
    const float*     in_b = (const float*)d_in[5];
    const float*     ow   = (const float*)d_in[6];
    const float*     ob   = (const float*)d_in[7];
    const float*     w1   = (const float*)d_in[8];
    const float*     b1   = (const float*)d_in[9];
    const float*     w2   = (const float*)d_in[10];
    const float*     b2   = (const float*)d_in[11];
    float* out = (float*)d_out;

    setup_kernel<<<1, 256>>>(rl);
    trans_kernel<<<(TOTC*QN + 255)/256, 256>>>(rp, ptm);
    ego_init_kernel<<<(NB*QN*(EN/4) + 255)/256, 256>>>(x);
    wkk_kernel<<<EN, EN>>>(in_w, in_b, w2, b2);
    table_kernel<<<dim3(3*NTAB/128, 2), 256>>>(w1);
    bev_lookup<<<(TOTC*QN*(EN/4) + 255)/256, 256>>>(b1);

    dim3 gcav(TOTC*QN/128, 2);
    mma_gemm<1,32><<<gcav, 256>>>(nullptr,       nullptr,    x, 0);   // kp (K=512)
    mma_gemm<2,16><<<gcav, 256>>>(in_w + 512*EN, in_b + 512, x, 0);   // vp

    dim3 gego(NB*QN/128, 2);
    int cur = 0;
    for (int it = 0; it < 2; it++) {
        mma_gemm<3,16><<<gego, 256>>>(in_w, in_b, x, cur);            // qp
        attn_kernel<<<NB*QN*NH*32/256, 256>>>();                      // ctx
        mma_gemm<4,16><<<gego, 256>>>(ow, ob, x, cur);                // ego
        cur ^= 1;
    }
    out_kernel<<<(QN*TOTC*(EN/4) + 255)/256, 256>>>(x, out, cur);
}